// round 8
// baseline (speedup 1.0000x reference)
#include <cuda_runtime.h>
#include <cuda_fp16.h>
#include <cstdint>

#define BATCH 16384
#define CODE  512
#define HID   1024

// ---------------- static device scratch ----------------
__device__ __half g_W[CODE*HID + 6*CODE*CODE];   // weights, fp16
__device__ __half g_Hhi[BATCH*HID];
__device__ __half g_Hlo[BATCH*HID];
__device__ __half g_Vhi[2][BATCH*CODE];
__device__ __half g_Vlo[2][BATCH*CODE];

// ---------------- helpers ----------------
__device__ __forceinline__ uint32_t smem_u32(const void* p) {
    uint32_t a;
    asm("{ .reg .u64 t; cvta.to.shared.u64 t, %1; cvt.u32.u64 %0, t; }" : "=r"(a) : "l"(p));
    return a;
}
__device__ __forceinline__ void ldsm4(uint32_t* r, uint32_t a) {
    asm volatile("ldmatrix.sync.aligned.m8n8.x4.shared.b16 {%0,%1,%2,%3}, [%4];"
        : "=r"(r[0]), "=r"(r[1]), "=r"(r[2]), "=r"(r[3]) : "r"(a));
}
__device__ __forceinline__ void mma16816(float* d, const uint32_t* a, uint32_t b0, uint32_t b1) {
    asm volatile("mma.sync.aligned.m16n8k16.row.col.f32.f16.f16.f32 "
        "{%0,%1,%2,%3},{%4,%5,%6,%7},{%8,%9},{%0,%1,%2,%3};"
        : "+f"(d[0]), "+f"(d[1]), "+f"(d[2]), "+f"(d[3])
        : "r"(a[0]), "r"(a[1]), "r"(a[2]), "r"(a[3]), "r"(b0), "r"(b1));
}
#define CP_ASYNC(s, g) asm volatile("cp.async.cg.shared.global [%0], [%1], 16;" :: "r"(s), "l"(g))
#define CP_COMMIT()    asm volatile("cp.async.commit_group;")
#define CP_WAIT1()     asm volatile("cp.async.wait_group 1;")

__device__ __forceinline__ void store_hl(__half* Vhi, __half* Vlo,
                                         size_t off, float v0, float v1) {
    __half h0 = __float2half_rn(v0), h1 = __float2half_rn(v1);
    __half l0 = __float2half_rn(v0 - __half2float(h0));
    __half l1 = __float2half_rn(v1 - __half2float(h1));
    *(__half2*)(Vhi + off) = __halves2half2(h0, h1);
    *(__half2*)(Vlo + off) = __halves2half2(l0, l1);
}

// ---------------- converters ----------------
__global__ void cvt_w(const float4* __restrict__ src, __half2* __restrict__ w, int n4) {
    int i = blockIdx.x * blockDim.x + threadIdx.x;
    if (i >= n4) return;
    float4 v = src[i];
    w[2*i]   = __halves2half2(__float2half_rn(v.x), __float2half_rn(v.y));
    w[2*i+1] = __halves2half2(__float2half_rn(v.z), __float2half_rn(v.w));
}
__global__ void cvt_a(const float4* __restrict__ src,
                      __half2* __restrict__ hi, __half2* __restrict__ lo, int n4) {
    int i = blockIdx.x * blockDim.x + threadIdx.x;
    if (i >= n4) return;
    float4 v = src[i];
    __half h0 = __float2half_rn(v.x), h1 = __float2half_rn(v.y);
    __half h2 = __float2half_rn(v.z), h3 = __float2half_rn(v.w);
    __half l0 = __float2half_rn(v.x - __half2float(h0));
    __half l1 = __float2half_rn(v.y - __half2float(h1));
    __half l2 = __float2half_rn(v.z - __half2float(h2));
    __half l3 = __float2half_rn(v.w - __half2float(h3));
    hi[2*i]   = __halves2half2(h0, h1);
    hi[2*i+1] = __halves2half2(h2, h3);
    lo[2*i]   = __halves2half2(l0, l1);
    lo[2*i+1] = __halves2half2(l2, l3);
}

// ---------------- GEMM: V = A @ W^T + bias, fp16 2-pass ----------------
// CTA tile 128x256, 8 warps as 2(m) x 4(n), warp tile 64x64.
// k-chunk 64, 3-stage cp.async pipeline. Stage = Ahi(16K)|Alo(16K)|W(32K).
#define A_SEC    16384
#define W_SEC    32768
#define STAGE_B  (2 * A_SEC + W_SEC)   // 65536
#define GSMEM    (3 * STAGE_B)         // 196608

template<int K>
__global__ void __launch_bounds__(256, 1)
gemm_layer(const __half* __restrict__ Ahi, const __half* __restrict__ Alo,
           const __half* __restrict__ W,
           const float* __restrict__ bias,
           __half* __restrict__ Vhi, __half* __restrict__ Vlo)
{
    extern __shared__ char sm[];
    const uint32_t sb = smem_u32(sm);
    const int tid = threadIdx.x, lane = tid & 31, wid = tid >> 5;
    const int wm = wid & 1, wn = wid >> 1;            // 2(m) x 4(n) warp grid
    const int m0 = blockIdx.x * 128, n0 = blockIdx.y * 256;
    constexpr int NITER = K / 64;

    // ---- gmem->smem staging: 16 x 16B chunks per thread ----
    const int lrow = tid >> 3, lc = tid & 7;           // lrow 0..31, lc 0..7
    const uint32_t sc = (uint32_t)((lc ^ (lrow & 7)) << 4);   // swizzled chunk (row&7 const mod 32)
    const char* gA_hi = (const char*)Ahi + (size_t)(m0 + lrow) * (K * 2) + lc * 16;
    const char* gA_lo = (const char*)Alo + (size_t)(m0 + lrow) * (K * 2) + lc * 16;
    const char* gW    = (const char*)W   + (size_t)(n0 + lrow) * (K * 2) + lc * 16;

    // ---- ldmatrix source rows ----
    int rA[4];
    #pragma unroll
    for (int mt = 0; mt < 4; mt++) rA[mt] = wm * 64 + mt * 16 + (lane & 15);
    const int cA = lane >> 4;
    int nB[4];
    #pragma unroll
    for (int p = 0; p < 4; p++) nB[p] = wn * 64 + p * 16 + (lane & 7) + ((lane >> 4) << 3);
    const int cB = (lane >> 3) & 1;

    float acc[32][4] = {};                             // 4(mt) x 8(nt)

    auto prefetch = [&](int it) {
        if (it < NITER) {
            const uint32_t slot = sb + (uint32_t)(it % 3) * STAGE_B;
            const uint32_t koff = (uint32_t)it * 128;
            #pragma unroll
            for (int q = 0; q < 4; q++) {
                const uint32_t so = (uint32_t)(lrow + q * 32) * 128 + sc;
                CP_ASYNC(slot + so,         gA_hi + (size_t)q * 32 * (K * 2) + koff);
                CP_ASYNC(slot + A_SEC + so, gA_lo + (size_t)q * 32 * (K * 2) + koff);
            }
            #pragma unroll
            for (int q = 0; q < 8; q++) {
                const uint32_t so = (uint32_t)(lrow + q * 32) * 128 + sc;
                CP_ASYNC(slot + 2 * A_SEC + so, gW + (size_t)q * 32 * (K * 2) + koff);
            }
        }
        CP_COMMIT();
    };

    prefetch(0);
    prefetch(1);

    for (int it = 0; it < NITER; it++) {
        CP_WAIT1();                    // stage `it` landed (this thread)
        __syncthreads();               // visible to all; slot (it+2)%3 free
        prefetch(it + 2);

        const uint32_t slot = sb + (uint32_t)(it % 3) * STAGE_B;
        #pragma unroll
        for (int ks = 0; ks < 4; ks++) {
            uint32_t ah[4][4], al[4][4];
            #pragma unroll
            for (int mt = 0; mt < 4; mt++) {
                const uint32_t ro = (uint32_t)rA[mt] * 128 +
                    (uint32_t)((((ks * 2 + cA) ^ (rA[mt] & 7))) << 4);
                ldsm4(ah[mt], slot + ro);
                ldsm4(al[mt], slot + A_SEC + ro);
            }
            #pragma unroll
            for (int p = 0; p < 4; p++) {
                const uint32_t ro = (uint32_t)nB[p] * 128 +
                    (uint32_t)((((ks * 2 + cB) ^ (nB[p] & 7))) << 4);
                uint32_t w[4];
                ldsm4(w, slot + 2 * A_SEC + ro);
                #pragma unroll
                for (int mt = 0; mt < 4; mt++) {
                    float* d0 = acc[mt * 8 + p * 2];
                    float* d1 = acc[mt * 8 + p * 2 + 1];
                    mma16816(d0, ah[mt], w[0], w[1]);
                    mma16816(d0, al[mt], w[0], w[1]);
                    mma16816(d1, ah[mt], w[2], w[3]);
                    mma16816(d1, al[mt], w[2], w[3]);
                }
            }
        }
    }

    // ---- epilogue: +bias, write v as fp16 hi/lo ----
    const int gid = lane >> 2, qid = lane & 3;
    #pragma unroll
    for (int nt = 0; nt < 8; nt++) {
        const int col = n0 + wn * 64 + nt * 8 + qid * 2;
        const float b0 = __ldg(bias + col), b1 = __ldg(bias + col + 1);
        #pragma unroll
        for (int mt = 0; mt < 4; mt++) {
            const float* d = acc[mt * 8 + nt];
            const int row = m0 + wm * 64 + mt * 16 + gid;
            store_hl(Vhi, Vlo, (size_t)row * CODE + col,       d[0] + b0, d[1] + b1);
            store_hl(Vhi, Vlo, (size_t)(row + 8) * CODE + col, d[2] + b0, d[3] + b1);
        }
    }
}

// ---------------- Householder: z -= 2 v (v.z)/(v.v), one warp per row ----------------
__global__ void __launch_bounds__(256)
hh_kernel(const __half* __restrict__ Vhi, const __half* __restrict__ Vlo,
          const float* __restrict__ z_in, float* __restrict__ z_out)
{
    const int lane = threadIdx.x & 31, warp = threadIdx.x >> 5;
    const size_t row = (size_t)blockIdx.x * 8 + warp;
    const __half* vh = Vhi + row * CODE;
    const __half* vl = Vlo + row * CODE;
    const float* zi = z_in + row * CODE;

    float v[16], z[16];
    float vz = 0.f, vv = 0.f;
    #pragma unroll
    for (int ch = 0; ch < 4; ch++) {
        const int c = ch * 128 + lane * 4;
        uint2 hp = *(const uint2*)(vh + c);
        uint2 lp = *(const uint2*)(vl + c);
        float4 zt = *(const float4*)(zi + c);
        float2 h0 = __half22float2(*(const __half2*)&hp.x);
        float2 h1 = __half22float2(*(const __half2*)&hp.y);
        float2 l0 = __half22float2(*(const __half2*)&lp.x);
        float2 l1 = __half22float2(*(const __half2*)&lp.y);
        v[ch*4+0] = h0.x + l0.x; v[ch*4+1] = h0.y + l0.y;
        v[ch*4+2] = h1.x + l1.x; v[ch*4+3] = h1.y + l1.y;
        z[ch*4+0] = zt.x; z[ch*4+1] = zt.y; z[ch*4+2] = zt.z; z[ch*4+3] = zt.w;
        #pragma unroll
        for (int j = 0; j < 4; j++) {
            vz += v[ch*4+j] * z[ch*4+j];
            vv += v[ch*4+j] * v[ch*4+j];
        }
    }
    #pragma unroll
    for (int o = 16; o; o >>= 1) {
        vz += __shfl_xor_sync(0xffffffffu, vz, o);
        vv += __shfl_xor_sync(0xffffffffu, vv, o);
    }
    const float s = 2.f * vz / vv;
    float* zo = z_out + row * CODE;
    #pragma unroll
    for (int ch = 0; ch < 4; ch++) {
        const int c = ch * 128 + lane * 4;
        float4 o;
        o.x = z[ch*4+0] - s * v[ch*4+0];
        o.y = z[ch*4+1] - s * v[ch*4+1];
        o.z = z[ch*4+2] - s * v[ch*4+2];
        o.w = z[ch*4+3] - s * v[ch*4+3];
        *(float4*)(zo + c) = o;
    }
}

// ---------------- stream/event context (created at load time; no device mem) --
struct HHCtx {
    cudaStream_t s = nullptr;
    cudaEvent_t fork = nullptr, wdone = nullptr, join = nullptr, g[7] = {};
    bool ok = false;
    HHCtx() {
        if (cudaStreamCreateWithFlags(&s, cudaStreamNonBlocking) != cudaSuccess) return;
        if (cudaEventCreateWithFlags(&fork,  cudaEventDisableTiming) != cudaSuccess) return;
        if (cudaEventCreateWithFlags(&wdone, cudaEventDisableTiming) != cudaSuccess) return;
        if (cudaEventCreateWithFlags(&join,  cudaEventDisableTiming) != cudaSuccess) return;
        for (int i = 0; i < 7; i++)
            if (cudaEventCreateWithFlags(&g[i], cudaEventDisableTiming) != cudaSuccess) return;
        ok = true;
    }
};
static HHCtx g_ctx;

// ---------------- host launch ----------------
extern "C" void kernel_launch(void* const* d_in, const int* in_sizes, int n_in,
                              void* d_out, int out_size)
{
    (void)in_sizes; (void)n_in; (void)out_size;
    const float* hidden = (const float*)d_in[0];
    const float* zs     = (const float*)d_in[1];
    const float* W0     = (const float*)d_in[2];
    const float* b0     = (const float*)d_in[3];
    const float* Ws     = (const float*)d_in[4];
    const float* bs     = (const float*)d_in[5];
    float* out = (float*)d_out;

    void *pW, *pHhi, *pHlo, *pVhi, *pVlo;
    cudaGetSymbolAddress(&pW,   g_W);
    cudaGetSymbolAddress(&pHhi, g_Hhi);
    cudaGetSymbolAddress(&pHlo, g_Hlo);
    cudaGetSymbolAddress(&pVhi, g_Vhi);
    cudaGetSymbolAddress(&pVlo, g_Vlo);
    __half* Wf   = (__half*)pW;
    __half* Hhi  = (__half*)pHhi;
    __half* Hlo  = (__half*)pHlo;
    __half* Vhi0 = (__half*)pVhi;
    __half* Vlo0 = (__half*)pVlo;
    __half* Vhi1 = Vhi0 + (size_t)BATCH * CODE;
    __half* Vlo1 = Vlo0 + (size_t)BATCH * CODE;

    cudaFuncSetAttribute(gemm_layer<HID>,  cudaFuncAttributeMaxDynamicSharedMemorySize, GSMEM);
    cudaFuncSetAttribute(gemm_layer<CODE>, cudaFuncAttributeMaxDynamicSharedMemorySize, GSMEM);

    const int nW0 = CODE * HID, nWs = 6 * CODE * CODE, nH = BATCH * HID;
    const dim3 ggrid(BATCH / 128, CODE / 256);   // 128 x 2
    const int hgrid = BATCH / 8;                 // 2048

    const bool fork_ok = g_ctx.ok;
    cudaStream_t sW  = fork_ok ? g_ctx.s : (cudaStream_t)0;
    cudaStream_t sHH = sW;

    if (fork_ok) {
        cudaEventRecord(g_ctx.fork, 0);
        cudaStreamWaitEvent(g_ctx.s, g_ctx.fork, 0);
    }
    cvt_w<<<(nW0/4 + 255)/256, 256, 0, sW>>>((const float4*)W0, (__half2*)Wf, nW0/4);
    cvt_w<<<(nWs/4 + 255)/256, 256, 0, sW>>>((const float4*)Ws, (__half2*)(Wf + nW0), nWs/4);
    cvt_a<<<(nH/4 + 255)/256, 256>>>((const float4*)hidden, (__half2*)Hhi, (__half2*)Hlo, nH/4);
    if (fork_ok) {
        cudaEventRecord(g_ctx.wdone, g_ctx.s);
        cudaStreamWaitEvent(0, g_ctx.wdone, 0);
    }

    gemm_layer<HID><<<ggrid, 256, GSMEM>>>(Hhi, Hlo, Wf, b0, Vhi0, Vlo0);
    if (fork_ok) {
        cudaEventRecord(g_ctx.g[0], 0);
        cudaStreamWaitEvent(g_ctx.s, g_ctx.g[0], 0);
    }
    hh_kernel<<<hgrid, 256, 0, sHH>>>(Vhi0, Vlo0, zs, out);

    __half *curHi = Vhi0, *curLo = Vlo0, *nxtHi = Vhi1, *nxtLo = Vlo1;
    for (int l = 1; l <= 6; l++) {
        const __half* Wl = Wf + nW0 + (size_t)(l - 1) * CODE * CODE;
        gemm_layer<CODE><<<ggrid, 256, GSMEM>>>(curHi, curLo, Wl,
                                                bs + (l - 1) * CODE, nxtHi, nxtLo);
        if (fork_ok) {
            cudaEventRecord(g_ctx.g[l], 0);
            cudaStreamWaitEvent(g_ctx.s, g_ctx.g[l], 0);
        }
        hh_kernel<<<hgrid, 256, 0, sHH>>>(nxtHi, nxtLo, out, out);
        __half* t;
        t = curHi; curHi = nxtHi; nxtHi = t;
        t = curLo; curLo = nxtLo; nxtLo = t;
    }

    if (fork_ok) {
        cudaEventRecord(g_ctx.join, g_ctx.s);
        cudaStreamWaitEvent(0, g_ctx.join, 0);
    }
}

// round 9
// speedup vs baseline: 1.0230x; 1.0230x over previous
#include <cuda_runtime.h>
#include <cuda_fp16.h>
#include <cstdint>

#define BATCH 16384
#define CODE  512
#define HID   1024

// ---------------- static device scratch ----------------
__device__ __half g_W[CODE*HID + 6*CODE*CODE];   // weights, fp16 single
__device__ __half g_Hhi[BATCH*HID];              // hidden hi
__device__ __half g_Hlo[BATCH*HID];              // hidden lo
__device__ __half g_Vhi[2][BATCH*CODE];
__device__ __half g_Vlo[2][BATCH*CODE];

// ---------------- helpers ----------------
__device__ __forceinline__ uint32_t smem_u32(const void* p) {
    uint32_t a;
    asm("{ .reg .u64 t; cvta.to.shared.u64 t, %1; cvt.u32.u64 %0, t; }" : "=r"(a) : "l"(p));
    return a;
}
__device__ __forceinline__ void ldsm4(uint32_t* r, uint32_t a) {
    asm volatile("ldmatrix.sync.aligned.m8n8.x4.shared.b16 {%0,%1,%2,%3}, [%4];"
        : "=r"(r[0]), "=r"(r[1]), "=r"(r[2]), "=r"(r[3]) : "r"(a));
}
__device__ __forceinline__ void mma16816(float* d, const uint32_t* a, uint32_t b0, uint32_t b1) {
    asm volatile("mma.sync.aligned.m16n8k16.row.col.f32.f16.f16.f32 "
        "{%0,%1,%2,%3},{%4,%5,%6,%7},{%8,%9},{%0,%1,%2,%3};"
        : "+f"(d[0]), "+f"(d[1]), "+f"(d[2]), "+f"(d[3])
        : "r"(a[0]), "r"(a[1]), "r"(a[2]), "r"(a[3]), "r"(b0), "r"(b1));
}
#define CP_ASYNC(s, g) asm volatile("cp.async.cg.shared.global [%0], [%1], 16;" :: "r"(s), "l"(g))
#define CP_COMMIT()    asm volatile("cp.async.commit_group;")
#define CP_WAIT1()     asm volatile("cp.async.wait_group 1;")

__device__ __forceinline__ void store_hl(__half* Vhi, __half* Vlo,
                                         size_t off, float v0, float v1) {
    __half h0 = __float2half_rn(v0), h1 = __float2half_rn(v1);
    __half l0 = __float2half_rn(v0 - __half2float(h0));
    __half l1 = __float2half_rn(v1 - __half2float(h1));
    *(__half2*)(Vhi + off) = __halves2half2(h0, h1);
    *(__half2*)(Vlo + off) = __halves2half2(l0, l1);
}

// ---------------- converters ----------------
__global__ void cvt_w(const float4* __restrict__ src, __half2* __restrict__ w, int n4) {
    int i = blockIdx.x * blockDim.x + threadIdx.x;
    if (i >= n4) return;
    float4 v = src[i];
    w[2*i]   = __halves2half2(__float2half_rn(v.x), __float2half_rn(v.y));
    w[2*i+1] = __halves2half2(__float2half_rn(v.z), __float2half_rn(v.w));
}
__global__ void cvt_a(const float4* __restrict__ src,
                      __half2* __restrict__ hi, __half2* __restrict__ lo, int n4) {
    int i = blockIdx.x * blockDim.x + threadIdx.x;
    if (i >= n4) return;
    float4 v = src[i];
    __half h0 = __float2half_rn(v.x), h1 = __float2half_rn(v.y);
    __half h2 = __float2half_rn(v.z), h3 = __float2half_rn(v.w);
    __half l0 = __float2half_rn(v.x - __half2float(h0));
    __half l1 = __float2half_rn(v.y - __half2float(h1));
    __half l2 = __float2half_rn(v.z - __half2float(h2));
    __half l3 = __float2half_rn(v.w - __half2float(h3));
    hi[2*i]   = __halves2half2(h0, h1);
    hi[2*i+1] = __halves2half2(h2, h3);
    lo[2*i]   = __halves2half2(l0, l1);
    lo[2*i+1] = __halves2half2(l2, l3);
}

// ---------------- GEMM: V = A @ W^T + bias, fp16 2-pass (Ahi+Alo) ----------------
// CTA tile 128x128, 8 warps of 64x32, k-chunk 64, 3-stage cp.async pipeline.
// Stage = Ahi|Alo|W (3 x 16KB, SW128). Frag register double-buffering.
// MMA issue order: all 16 hi-pass MMAs, then all 16 lo-pass MMAs, so the
// same accumulator is never written by two adjacent HMMAs (RAW distance 16).
#define SEC_B    16384
#define STAGE_B  (3 * SEC_B)           // 49152
#define GSMEM    (3 * STAGE_B)         // 147456

template<int K>
__global__ void __launch_bounds__(256, 1)
gemm_layer(const __half* __restrict__ Ahi, const __half* __restrict__ Alo,
           const __half* __restrict__ W,
           const float* __restrict__ bias,
           __half* __restrict__ Vhi, __half* __restrict__ Vlo)
{
    extern __shared__ char sm[];
    const uint32_t sb = smem_u32(sm);
    const int tid = threadIdx.x, lane = tid & 31, wid = tid >> 5;
    const int wm = wid & 1, wn = wid >> 1;            // 2 x 4 warp grid
    const int m0 = blockIdx.x * 128, n0 = blockIdx.y * 128;
    constexpr int NITER = K / 64;

    // ---- gmem->smem load offsets (per thread: 4 x 16B per section) ----
    const int lrow = tid >> 3, lc = tid & 7;
    uint32_t sOff[4], gAo[4], gBo[4];
    #pragma unroll
    for (int q = 0; q < 4; q++) {
        int row = lrow + q * 32;
        sOff[q] = (uint32_t)row * 128 + (uint32_t)((lc ^ (row & 7)) << 4);
        gAo[q] = (uint32_t)(m0 + row) * (K * 2) + lc * 16;
        gBo[q] = (uint32_t)(n0 + row) * (K * 2) + lc * 16;
    }

    // ---- ldmatrix source rows ----
    int rA[4];
    #pragma unroll
    for (int mt = 0; mt < 4; mt++) rA[mt] = wm * 64 + mt * 16 + (lane & 15);
    const int cA = lane >> 4;
    int nB[2];
    #pragma unroll
    for (int p = 0; p < 2; p++) nB[p] = wn * 32 + p * 16 + (lane & 7) + ((lane >> 4) << 3);
    const int cB = (lane >> 3) & 1;

    // ---- bias preload ----
    const int gid = lane >> 2, qid = lane & 3;
    float bcol[8];
    #pragma unroll
    for (int nt = 0; nt < 4; nt++) {
        const int col = n0 + wn * 32 + nt * 8 + qid * 2;
        bcol[nt * 2]     = __ldg(bias + col);
        bcol[nt * 2 + 1] = __ldg(bias + col + 1);
    }

    float acc[16][4] = {};

    auto prefetch = [&](int it) {
        if (it < NITER) {
            const uint32_t slot = sb + (uint32_t)(it % 3) * STAGE_B;
            const uint32_t koff = (uint32_t)it * 128;
            #pragma unroll
            for (int q = 0; q < 4; q++) {
                CP_ASYNC(slot + 0*SEC_B + sOff[q], (const char*)Ahi + gAo[q] + koff);
                CP_ASYNC(slot + 1*SEC_B + sOff[q], (const char*)Alo + gAo[q] + koff);
                CP_ASYNC(slot + 2*SEC_B + sOff[q], (const char*)W   + gBo[q] + koff);
            }
        }
        CP_COMMIT();
    };

    // fragment double buffers
    uint32_t ah[2][4][4], al[2][4][4], w[2][2][4];

    auto load_frags = [&](int buf, uint32_t slot, int ks) {
        #pragma unroll
        for (int mt = 0; mt < 4; mt++) {
            const uint32_t ro = (uint32_t)rA[mt] * 128 +
                (uint32_t)((((ks * 2 + cA) ^ (rA[mt] & 7))) << 4);
            ldsm4(ah[buf][mt], slot + 0*SEC_B + ro);
            ldsm4(al[buf][mt], slot + 1*SEC_B + ro);
        }
        #pragma unroll
        for (int p = 0; p < 2; p++) {
            const uint32_t ro = (uint32_t)nB[p] * 128 +
                (uint32_t)((((ks * 2 + cB) ^ (nB[p] & 7))) << 4);
            ldsm4(w[buf][p], slot + 2*SEC_B + ro);
        }
    };

    auto mma_block = [&](int buf) {
        // hi pass: 16 independent accumulators back-to-back
        #pragma unroll
        for (int mt = 0; mt < 4; mt++) {
            #pragma unroll
            for (int nt = 0; nt < 4; nt++) {
                const uint32_t w0 = w[buf][nt >> 1][(nt & 1) * 2];
                const uint32_t w1 = w[buf][nt >> 1][(nt & 1) * 2 + 1];
                mma16816(acc[mt * 4 + nt], ah[buf][mt], w0, w1);
            }
        }
        // lo pass: same accumulators, RAW distance = 16 HMMAs
        #pragma unroll
        for (int mt = 0; mt < 4; mt++) {
            #pragma unroll
            for (int nt = 0; nt < 4; nt++) {
                const uint32_t w0 = w[buf][nt >> 1][(nt & 1) * 2];
                const uint32_t w1 = w[buf][nt >> 1][(nt & 1) * 2 + 1];
                mma16816(acc[mt * 4 + nt], al[buf][mt], w0, w1);
            }
        }
    };

    prefetch(0);
    prefetch(1);

    for (int it = 0; it < NITER; it++) {
        CP_WAIT1();                    // stage `it` landed (this thread)
        __syncthreads();               // stage `it` visible; slot (it+2)%3 free
        prefetch(it + 2);

        const uint32_t slot = sb + (uint32_t)(it % 3) * STAGE_B;
        load_frags(0, slot, 0);
        #pragma unroll
        for (int ks = 0; ks < 4; ks++) {
            if (ks < 3) load_frags((ks + 1) & 1, slot, ks + 1);
            mma_block(ks & 1);
        }
    }

    // ---- epilogue: +bias, write v as fp16 hi/lo ----
    #pragma unroll
    for (int mt = 0; mt < 4; mt++) {
        #pragma unroll
        for (int nt = 0; nt < 4; nt++) {
            const float* d = acc[mt * 4 + nt];
            const int row = m0 + wm * 64 + mt * 16 + gid;
            const int col = n0 + wn * 32 + nt * 8 + qid * 2;
            const float b0 = bcol[nt * 2], b1 = bcol[nt * 2 + 1];
            store_hl(Vhi, Vlo, (size_t)row * CODE + col,       d[0] + b0, d[1] + b1);
            store_hl(Vhi, Vlo, (size_t)(row + 8) * CODE + col, d[2] + b0, d[3] + b1);
        }
    }
}

// ---------------- Householder: z -= 2 v (v.z)/(v.v), one warp per row ----------------
__global__ void __launch_bounds__(256)
hh_kernel(const __half* __restrict__ Vhi, const __half* __restrict__ Vlo,
          const float* __restrict__ z_in, float* __restrict__ z_out)
{
    const int lane = threadIdx.x & 31, warp = threadIdx.x >> 5;
    const size_t row = (size_t)blockIdx.x * 8 + warp;
    const __half* vh = Vhi + row * CODE;
    const __half* vl = Vlo + row * CODE;
    const float* zi = z_in + row * CODE;

    float v[16], z[16];
    float vz = 0.f, vv = 0.f;
    #pragma unroll
    for (int ch = 0; ch < 4; ch++) {
        const int c = ch * 128 + lane * 4;
        uint2 hp = *(const uint2*)(vh + c);
        uint2 lp = *(const uint2*)(vl + c);
        float4 zt = *(const float4*)(zi + c);
        float2 h0 = __half22float2(*(const __half2*)&hp.x);
        float2 h1 = __half22float2(*(const __half2*)&hp.y);
        float2 l0 = __half22float2(*(const __half2*)&lp.x);
        float2 l1 = __half22float2(*(const __half2*)&lp.y);
        v[ch*4+0] = h0.x + l0.x; v[ch*4+1] = h0.y + l0.y;
        v[ch*4+2] = h1.x + l1.x; v[ch*4+3] = h1.y + l1.y;
        z[ch*4+0] = zt.x; z[ch*4+1] = zt.y; z[ch*4+2] = zt.z; z[ch*4+3] = zt.w;
        #pragma unroll
        for (int j = 0; j < 4; j++) {
            vz += v[ch*4+j] * z[ch*4+j];
            vv += v[ch*4+j] * v[ch*4+j];
        }
    }
    #pragma unroll
    for (int o = 16; o; o >>= 1) {
        vz += __shfl_xor_sync(0xffffffffu, vz, o);
        vv += __shfl_xor_sync(0xffffffffu, vv, o);
    }
    const float s = 2.f * vz / vv;
    float* zo = z_out + row * CODE;
    #pragma unroll
    for (int ch = 0; ch < 4; ch++) {
        const int c = ch * 128 + lane * 4;
        float4 o;
        o.x = z[ch*4+0] - s * v[ch*4+0];
        o.y = z[ch*4+1] - s * v[ch*4+1];
        o.z = z[ch*4+2] - s * v[ch*4+2];
        o.w = z[ch*4+3] - s * v[ch*4+3];
        *(float4*)(zo + c) = o;
    }
}

// ---------------- stream/event context (created at load time; no device mem) --
struct HHCtx {
    cudaStream_t s = nullptr;
    cudaEvent_t fork = nullptr, wdone = nullptr, join = nullptr, g[7] = {};
    bool ok = false;
    HHCtx() {
        if (cudaStreamCreateWithFlags(&s, cudaStreamNonBlocking) != cudaSuccess) return;
        if (cudaEventCreateWithFlags(&fork,  cudaEventDisableTiming) != cudaSuccess) return;
        if (cudaEventCreateWithFlags(&wdone, cudaEventDisableTiming) != cudaSuccess) return;
        if (cudaEventCreateWithFlags(&join,  cudaEventDisableTiming) != cudaSuccess) return;
        for (int i = 0; i < 7; i++)
            if (cudaEventCreateWithFlags(&g[i], cudaEventDisableTiming) != cudaSuccess) return;
        ok = true;
    }
};
static HHCtx g_ctx;

// ---------------- host launch ----------------
extern "C" void kernel_launch(void* const* d_in, const int* in_sizes, int n_in,
                              void* d_out, int out_size)
{
    (void)in_sizes; (void)n_in; (void)out_size;
    const float* hidden = (const float*)d_in[0];
    const float* zs     = (const float*)d_in[1];
    const float* W0     = (const float*)d_in[2];
    const float* b0     = (const float*)d_in[3];
    const float* Ws     = (const float*)d_in[4];
    const float* bs     = (const float*)d_in[5];
    float* out = (float*)d_out;

    void *pW, *pHhi, *pHlo, *pVhi, *pVlo;
    cudaGetSymbolAddress(&pW,   g_W);
    cudaGetSymbolAddress(&pHhi, g_Hhi);
    cudaGetSymbolAddress(&pHlo, g_Hlo);
    cudaGetSymbolAddress(&pVhi, g_Vhi);
    cudaGetSymbolAddress(&pVlo, g_Vlo);
    __half* Wf   = (__half*)pW;
    __half* Hhi  = (__half*)pHhi;
    __half* Hlo  = (__half*)pHlo;
    __half* Vhi0 = (__half*)pVhi;
    __half* Vlo0 = (__half*)pVlo;
    __half* Vhi1 = Vhi0 + (size_t)BATCH * CODE;
    __half* Vlo1 = Vlo0 + (size_t)BATCH * CODE;

    cudaFuncSetAttribute(gemm_layer<HID>,  cudaFuncAttributeMaxDynamicSharedMemorySize, GSMEM);
    cudaFuncSetAttribute(gemm_layer<CODE>, cudaFuncAttributeMaxDynamicSharedMemorySize, GSMEM);

    const int nW0 = CODE * HID, nWs = 6 * CODE * CODE, nH = BATCH * HID;
    const dim3 ggrid(BATCH / 128, CODE / 128);   // 128 x 4
    const int hgrid = BATCH / 8;                 // 2048

    const bool fork_ok = g_ctx.ok;
    cudaStream_t sW  = fork_ok ? g_ctx.s : (cudaStream_t)0;
    cudaStream_t sHH = sW;

    if (fork_ok) {
        cudaEventRecord(g_ctx.fork, 0);
        cudaStreamWaitEvent(g_ctx.s, g_ctx.fork, 0);
    }
    cvt_w<<<(nW0/4 + 255)/256, 256, 0, sW>>>((const float4*)W0, (__half2*)Wf, nW0/4);
    cvt_w<<<(nWs/4 + 255)/256, 256, 0, sW>>>((const float4*)Ws, (__half2*)(Wf + nW0), nWs/4);
    cvt_a<<<(nH/4 + 255)/256, 256>>>((const float4*)hidden, (__half2*)Hhi, (__half2*)Hlo, nH/4);
    if (fork_ok) {
        cudaEventRecord(g_ctx.wdone, g_ctx.s);
        cudaStreamWaitEvent(0, g_ctx.wdone, 0);
    }

    gemm_layer<HID><<<ggrid, 256, GSMEM>>>(Hhi, Hlo, Wf, b0, Vhi0, Vlo0);
    if (fork_ok) {
        cudaEventRecord(g_ctx.g[0], 0);
        cudaStreamWaitEvent(g_ctx.s, g_ctx.g[0], 0);
    }
    hh_kernel<<<hgrid, 256, 0, sHH>>>(Vhi0, Vlo0, zs, out);

    __half *curHi = Vhi0, *curLo = Vlo0, *nxtHi = Vhi1, *nxtLo = Vlo1;
    for (int l = 1; l <= 6; l++) {
        const __half* Wl = Wf + nW0 + (size_t)(l - 1) * CODE * CODE;
        gemm_layer<CODE><<<ggrid, 256, GSMEM>>>(curHi, curLo, Wl,
                                                bs + (l - 1) * CODE, nxtHi, nxtLo);
        if (fork_ok) {
            cudaEventRecord(g_ctx.g[l], 0);
            cudaStreamWaitEvent(g_ctx.s, g_ctx.g[l], 0);
        }
        hh_kernel<<<hgrid, 256, 0, sHH>>>(nxtHi, nxtLo, out, out);
        __half* t;
        t = curHi; curHi = nxtHi; nxtHi = t;
        t = curLo; curLo = nxtLo; nxtLo = t;
    }

    if (fork_ok) {
        cudaEventRecord(g_ctx.join, g_ctx.s);
        cudaStreamWaitEvent(0, g_ctx.join, 0);
    }
}

// round 10
// speedup vs baseline: 1.9124x; 1.8694x over previous
#include <cuda_runtime.h>
#include <cuda_fp16.h>
#include <cstdint>

#define BATCH 16384
#define CODE  512
#define HID   1024

// ---------------- static device scratch ----------------
__device__ __half g_W[CODE*HID + 6*CODE*CODE];   // weights, fp16
__device__ __half g_H[BATCH*HID];                // hidden, fp16
__device__ __half g_V[2][BATCH*CODE];            // v ping-pong, fp16

// ---------------- helpers ----------------
__device__ __forceinline__ uint32_t smem_u32(const void* p) {
    uint32_t a;
    asm("{ .reg .u64 t; cvta.to.shared.u64 t, %1; cvt.u32.u64 %0, t; }" : "=r"(a) : "l"(p));
    return a;
}
__device__ __forceinline__ void ldsm4(uint32_t* r, uint32_t a) {
    asm volatile("ldmatrix.sync.aligned.m8n8.x4.shared.b16 {%0,%1,%2,%3}, [%4];"
        : "=r"(r[0]), "=r"(r[1]), "=r"(r[2]), "=r"(r[3]) : "r"(a));
}
__device__ __forceinline__ void mma16816(float* d, const uint32_t* a, uint32_t b0, uint32_t b1) {
    asm volatile("mma.sync.aligned.m16n8k16.row.col.f32.f16.f16.f32 "
        "{%0,%1,%2,%3},{%4,%5,%6,%7},{%8,%9},{%0,%1,%2,%3};"
        : "+f"(d[0]), "+f"(d[1]), "+f"(d[2]), "+f"(d[3])
        : "r"(a[0]), "r"(a[1]), "r"(a[2]), "r"(a[3]), "r"(b0), "r"(b1));
}
#define CP_ASYNC(s, g) asm volatile("cp.async.cg.shared.global [%0], [%1], 16;" :: "r"(s), "l"(g))
#define CP_COMMIT()    asm volatile("cp.async.commit_group;")
#define CP_WAIT1()     asm volatile("cp.async.wait_group 1;")

// ---------------- converter: fp32 -> fp16 ----------------
__global__ void cvt_h(const float4* __restrict__ src, __half2* __restrict__ w, int n4) {
    int i = blockIdx.x * blockDim.x + threadIdx.x;
    if (i >= n4) return;
    float4 v = src[i];
    w[2*i]   = __halves2half2(__float2half_rn(v.x), __float2half_rn(v.y));
    w[2*i+1] = __halves2half2(__float2half_rn(v.z), __float2half_rn(v.w));
}

// ---------------- GEMM: V = A @ W^T + bias, fp16 single-pass ----------------
// CTA tile 128x128, 8 warps of 64x32, k-chunk 64, 3-stage cp.async pipeline,
// 2 CTAs/SM. Stage = A(16K)|W(16K), SW128 swizzle.
#define SEC_B    16384
#define STAGE_B  (2 * SEC_B)           // 32768
#define GSMEM    (3 * STAGE_B)         // 98304

template<int K>
__global__ void __launch_bounds__(256, 2)
gemm_layer(const __half* __restrict__ A, const __half* __restrict__ W,
           const float* __restrict__ bias, __half* __restrict__ Vout)
{
    extern __shared__ char sm[];
    const uint32_t sb = smem_u32(sm);
    const int tid = threadIdx.x, lane = tid & 31, wid = tid >> 5;
    const int wm = wid & 1, wn = wid >> 1;            // 2 x 4 warp grid
    const int m0 = blockIdx.x * 128, n0 = blockIdx.y * 128;
    constexpr int NITER = K / 64;

    // ---- gmem->smem load offsets (per thread: 4 x 16B per section) ----
    const int lrow = tid >> 3, lc = tid & 7;
    uint32_t sOff[4], gAo[4], gBo[4];
    #pragma unroll
    for (int q = 0; q < 4; q++) {
        int row = lrow + q * 32;
        sOff[q] = (uint32_t)row * 128 + (uint32_t)((lc ^ (row & 7)) << 4);
        gAo[q] = (uint32_t)(m0 + row) * (K * 2) + lc * 16;
        gBo[q] = (uint32_t)(n0 + row) * (K * 2) + lc * 16;
    }

    // ---- ldmatrix source rows ----
    int rA[4];
    #pragma unroll
    for (int mt = 0; mt < 4; mt++) rA[mt] = wm * 64 + mt * 16 + (lane & 15);
    const int cA = lane >> 4;
    int nB[2];
    #pragma unroll
    for (int p = 0; p < 2; p++) nB[p] = wn * 32 + p * 16 + (lane & 7) + ((lane >> 4) << 3);
    const int cB = (lane >> 3) & 1;

    // ---- bias preload ----
    const int gid = lane >> 2, qid = lane & 3;
    float bcol[8];
    #pragma unroll
    for (int nt = 0; nt < 4; nt++) {
        const int col = n0 + wn * 32 + nt * 8 + qid * 2;
        bcol[nt * 2]     = __ldg(bias + col);
        bcol[nt * 2 + 1] = __ldg(bias + col + 1);
    }

    float acc[16][4] = {};

    auto prefetch = [&](int it) {
        if (it < NITER) {
            const uint32_t slot = sb + (uint32_t)(it % 3) * STAGE_B;
            const uint32_t koff = (uint32_t)it * 128;
            #pragma unroll
            for (int q = 0; q < 4; q++) {
                CP_ASYNC(slot + sOff[q],         (const char*)A + gAo[q] + koff);
                CP_ASYNC(slot + SEC_B + sOff[q], (const char*)W + gBo[q] + koff);
            }
        }
        CP_COMMIT();
    };

    prefetch(0);
    prefetch(1);

    for (int it = 0; it < NITER; it++) {
        CP_WAIT1();                    // stage `it` landed (this thread)
        __syncthreads();               // stage `it` visible; slot (it+2)%3 free
        prefetch(it + 2);

        const uint32_t slot = sb + (uint32_t)(it % 3) * STAGE_B;
        #pragma unroll
        for (int ks = 0; ks < 4; ks++) {
            uint32_t a[4][4], w[2][4];
            #pragma unroll
            for (int mt = 0; mt < 4; mt++) {
                const uint32_t ro = (uint32_t)rA[mt] * 128 +
                    (uint32_t)((((ks * 2 + cA) ^ (rA[mt] & 7))) << 4);
                ldsm4(a[mt], slot + ro);
            }
            #pragma unroll
            for (int p = 0; p < 2; p++) {
                const uint32_t ro = (uint32_t)nB[p] * 128 +
                    (uint32_t)((((ks * 2 + cB) ^ (nB[p] & 7))) << 4);
                ldsm4(w[p], slot + SEC_B + ro);
            }
            #pragma unroll
            for (int mt = 0; mt < 4; mt++) {
                #pragma unroll
                for (int nt = 0; nt < 4; nt++) {
                    mma16816(acc[mt * 4 + nt], a[mt],
                             w[nt >> 1][(nt & 1) * 2], w[nt >> 1][(nt & 1) * 2 + 1]);
                }
            }
        }
    }

    // ---- epilogue: +bias, write v as fp16 ----
    #pragma unroll
    for (int mt = 0; mt < 4; mt++) {
        #pragma unroll
        for (int nt = 0; nt < 4; nt++) {
            const float* d = acc[mt * 4 + nt];
            const int row = m0 + wm * 64 + mt * 16 + gid;
            const int col = n0 + wn * 32 + nt * 8 + qid * 2;
            const float b0 = bcol[nt * 2], b1 = bcol[nt * 2 + 1];
            *(__half2*)(Vout + (size_t)row * CODE + col) =
                __halves2half2(__float2half_rn(d[0] + b0), __float2half_rn(d[1] + b1));
            *(__half2*)(Vout + (size_t)(row + 8) * CODE + col) =
                __halves2half2(__float2half_rn(d[2] + b0), __float2half_rn(d[3] + b1));
        }
    }
}

// ---------------- Householder: z -= 2 v (v.z)/(v.v), one warp per row ----------------
__global__ void __launch_bounds__(256)
hh_kernel(const __half* __restrict__ V,
          const float* __restrict__ z_in, float* __restrict__ z_out)
{
    const int lane = threadIdx.x & 31, warp = threadIdx.x >> 5;
    const size_t row = (size_t)blockIdx.x * 8 + warp;
    const __half* vp = V + row * CODE;
    const float* zi = z_in + row * CODE;

    float v[16], z[16];
    float vz = 0.f, vv = 0.f;
    #pragma unroll
    for (int ch = 0; ch < 4; ch++) {
        const int c = ch * 128 + lane * 4;
        uint2 hp = *(const uint2*)(vp + c);
        float4 zt = *(const float4*)(zi + c);
        float2 h0 = __half22float2(*(const __half2*)&hp.x);
        float2 h1 = __half22float2(*(const __half2*)&hp.y);
        v[ch*4+0] = h0.x; v[ch*4+1] = h0.y; v[ch*4+2] = h1.x; v[ch*4+3] = h1.y;
        z[ch*4+0] = zt.x; z[ch*4+1] = zt.y; z[ch*4+2] = zt.z; z[ch*4+3] = zt.w;
        #pragma unroll
        for (int j = 0; j < 4; j++) {
            vz += v[ch*4+j] * z[ch*4+j];
            vv += v[ch*4+j] * v[ch*4+j];
        }
    }
    #pragma unroll
    for (int o = 16; o; o >>= 1) {
        vz += __shfl_xor_sync(0xffffffffu, vz, o);
        vv += __shfl_xor_sync(0xffffffffu, vv, o);
    }
    const float s = 2.f * vz / vv;
    float* zo = z_out + row * CODE;
    #pragma unroll
    for (int ch = 0; ch < 4; ch++) {
        const int c = ch * 128 + lane * 4;
        float4 o;
        o.x = z[ch*4+0] - s * v[ch*4+0];
        o.y = z[ch*4+1] - s * v[ch*4+1];
        o.z = z[ch*4+2] - s * v[ch*4+2];
        o.w = z[ch*4+3] - s * v[ch*4+3];
        *(float4*)(zo + c) = o;
    }
}

// ---------------- stream/event context (created at load time; no device mem) --
struct HHCtx {
    cudaStream_t s = nullptr;
    cudaEvent_t fork = nullptr, wdone = nullptr, join = nullptr, g[7] = {};
    bool ok = false;
    HHCtx() {
        if (cudaStreamCreateWithFlags(&s, cudaStreamNonBlocking) != cudaSuccess) return;
        if (cudaEventCreateWithFlags(&fork,  cudaEventDisableTiming) != cudaSuccess) return;
        if (cudaEventCreateWithFlags(&wdone, cudaEventDisableTiming) != cudaSuccess) return;
        if (cudaEventCreateWithFlags(&join,  cudaEventDisableTiming) != cudaSuccess) return;
        for (int i = 0; i < 7; i++)
            if (cudaEventCreateWithFlags(&g[i], cudaEventDisableTiming) != cudaSuccess) return;
        ok = true;
    }
};
static HHCtx g_ctx;

// ---------------- host launch ----------------
extern "C" void kernel_launch(void* const* d_in, const int* in_sizes, int n_in,
                              void* d_out, int out_size)
{
    (void)in_sizes; (void)n_in; (void)out_size;
    const float* hidden = (const float*)d_in[0];
    const float* zs     = (const float*)d_in[1];
    const float* W0     = (const float*)d_in[2];
    const float* b0     = (const float*)d_in[3];
    const float* Ws     = (const float*)d_in[4];
    const float* bs     = (const float*)d_in[5];
    float* out = (float*)d_out;

    void *pW, *pH, *pV;
    cudaGetSymbolAddress(&pW, g_W);
    cudaGetSymbolAddress(&pH, g_H);
    cudaGetSymbolAddress(&pV, g_V);
    __half* Wf = (__half*)pW;
    __half* Hf = (__half*)pH;
    __half* V0 = (__half*)pV;
    __half* V1 = V0 + (size_t)BATCH * CODE;

    cudaFuncSetAttribute(gemm_layer<HID>,  cudaFuncAttributeMaxDynamicSharedMemorySize, GSMEM);
    cudaFuncSetAttribute(gemm_layer<CODE>, cudaFuncAttributeMaxDynamicSharedMemorySize, GSMEM);

    const int nW0 = CODE * HID, nWs = 6 * CODE * CODE, nH = BATCH * HID;
    const dim3 ggrid(BATCH / 128, CODE / 128);   // 128 x 4
    const int hgrid = BATCH / 8;                 // 2048

    const bool fork_ok = g_ctx.ok;
    cudaStream_t sW  = fork_ok ? g_ctx.s : (cudaStream_t)0;
    cudaStream_t sHH = sW;

    if (fork_ok) {
        cudaEventRecord(g_ctx.fork, 0);
        cudaStreamWaitEvent(g_ctx.s, g_ctx.fork, 0);
    }
    cvt_h<<<(nW0/4 + 255)/256, 256, 0, sW>>>((const float4*)W0, (__half2*)Wf, nW0/4);
    cvt_h<<<(nWs/4 + 255)/256, 256, 0, sW>>>((const float4*)Ws, (__half2*)(Wf + nW0), nWs/4);
    cvt_h<<<(nH/4 + 255)/256, 256>>>((const float4*)hidden, (__half2*)Hf, nH/4);
    if (fork_ok) {
        cudaEventRecord(g_ctx.wdone, g_ctx.s);
        cudaStreamWaitEvent(0, g_ctx.wdone, 0);
    }

    gemm_layer<HID><<<ggrid, 256, GSMEM>>>(Hf, Wf, b0, V0);
    if (fork_ok) {
        cudaEventRecord(g_ctx.g[0], 0);
        cudaStreamWaitEvent(g_ctx.s, g_ctx.g[0], 0);
    }
    hh_kernel<<<hgrid, 256, 0, sHH>>>(V0, zs, out);

    __half *cur = V0, *nxt = V1;
    for (int l = 1; l <= 6; l++) {
        const __half* Wl = Wf + nW0 + (size_t)(l - 1) * CODE * CODE;
        gemm_layer<CODE><<<ggrid, 256, GSMEM>>>(cur, Wl, bs + (l - 1) * CODE, nxt);
        if (fork_ok) {
            cudaEventRecord(g_ctx.g[l], 0);
            cudaStreamWaitEvent(g_ctx.s, g_ctx.g[l], 0);
        }
        hh_kernel<<<hgrid, 256, 0, sHH>>>(nxt, out, out);
        __half* t = cur; cur = nxt; nxt = t;
    }

    if (fork_ok) {
        cudaEventRecord(g_ctx.join, g_ctx.s);
        cudaStreamWaitEvent(0, g_ctx.join, 0);
    }
}